// round 12
// baseline (speedup 1.0000x reference)
#include <cuda_runtime.h>
#include <math.h>
#include <stdint.h>

#define BB   32
#define NTOK 1024
#define CCH  256
#define HH   4
#define DD   64
#define FF   1024
#define MROWS (BB * NTOK)   // 32768
#define EPSV 1e-5f

// ---------------- static device scratch ----------------
__device__ float g_acc[1024];
__device__ float g_scale1[CCH], g_shift1[CCH];
__device__ float g_scale2[CCH], g_shift2[CCH];
__device__ float g_XN [(size_t)MROWS * CCH];  // BN1-normalized x
__device__ float g_H2 [(size_t)MROWS * CCH];  // BN2-normalized R1
__device__ float g_Q  [(size_t)MROWS * CCH];  // (B,H,N,D)
__device__ float g_K  [(size_t)MROWS * CCH];
__device__ float g_V  [(size_t)MROWS * CCH];
__device__ float g_AO [(size_t)MROWS * CCH];
__device__ float g_R1 [(size_t)MROWS * CCH];
__device__ float g_MID[(size_t)MROWS * FF];

// ---------------- small kernels ----------------
__global__ void zero_acc_kernel() {
    g_acc[threadIdx.x] = 0.f;
}

// partial channel sums; off=0 -> BN1 slots, off=512 -> BN2 slots
__global__ void bn_stats_kernel(const float* __restrict__ x, int off) {
    int c  = threadIdx.x;
    int r0 = blockIdx.x * 128;
    const float* p = x + (size_t)r0 * CCH + c;
    float s = 0.f, q = 0.f;
#pragma unroll 4
    for (int i = 0; i < 128; i++) {
        float v = p[(size_t)i * CCH];
        s += v;
        q += v * v;
    }
    atomicAdd(&g_acc[off + c],       s);
    atomicAdd(&g_acc[off + CCH + c], q);
}

__global__ void bn_finalize_kernel(const float* __restrict__ g,
                                   const float* __restrict__ beta, int which) {
    int c = threadIdx.x;
    float invn = 1.f / (float)MROWS;
    float mean = g_acc[which * 512 + c] * invn;
    float var  = g_acc[which * 512 + 256 + c] * invn - mean * mean;
    float sc   = g[c] * rsqrtf(var + EPSV);
    float sh   = beta[c] - mean * sc;
    if (which == 0) { g_scale1[c] = sc; g_shift1[c] = sh; }
    else            { g_scale2[c] = sc; g_shift2[c] = sh; }
}

__global__ __launch_bounds__(256)
void normalize_kernel(const float* __restrict__ in, float* __restrict__ out, int which) {
    const int idx = blockIdx.x * 256 + threadIdx.x;
    const int c = (idx * 4) & (CCH - 1);
    const float* sc = which ? g_scale2 : g_scale1;
    const float* sh = which ? g_shift2 : g_shift1;
    float4 v = ((const float4*)in)[idx];
    float4 o;
    o.x = v.x * sc[c]     + sh[c];
    o.y = v.y * sc[c + 1] + sh[c + 1];
    o.z = v.z * sc[c + 2] + sh[c + 2];
    o.w = v.w * sc[c + 3] + sh[c + 3];
    ((float4*)out)[idx] = o;
}

// ---------------- tf32 helpers ----------------
__device__ __forceinline__ uint32_t f2tf(float x) {
    uint32_t r;
    asm("cvt.rna.tf32.f32 %0, %1;" : "=r"(r) : "f"(x));
    return r;
}

__device__ __forceinline__ void mma8(float* c, const uint32_t* a, const uint32_t* b) {
    asm volatile(
        "mma.sync.aligned.m16n8k8.row.col.f32.tf32.tf32.f32 "
        "{%0,%1,%2,%3}, {%4,%5,%6,%7}, {%8,%9}, {%0,%1,%2,%3};"
        : "+f"(c[0]), "+f"(c[1]), "+f"(c[2]), "+f"(c[3])
        : "r"(a[0]), "r"(a[1]), "r"(a[2]), "r"(a[3]), "r"(b[0]), "r"(b[1]));
}

__device__ __forceinline__ void ldsm_x4(uint32_t* r, uint32_t addr) {
    asm volatile("ldmatrix.sync.aligned.m8n8.x4.shared.b16 {%0,%1,%2,%3}, [%4];"
                 : "=r"(r[0]), "=r"(r[1]), "=r"(r[2]), "=r"(r[3]) : "r"(addr));
}

#define CP16(dst, src) \
    asm volatile("cp.async.cg.shared.global [%0], [%1], 16;" :: "r"(dst), "l"(src))
#define CPCOMMIT() asm volatile("cp.async.commit_group;")
#define CPWAIT1()  asm volatile("cp.async.wait_group 1;")

// ---------------- tf32 tensor-core NT GEMM ----------------
// CTA tile 128x256, BK=32, 8 warps of 64x64 (2x4 grid), 1 CTA/SM.
// 3-stage cp.async (49152 B/stage), ldmatrix fragment feeds.
// EPI: 1 = +bias, store (B,H,N,D)   2 = +bias+res, store row-major
//      3 = +bias, ReLU              4 = +bias+res (final out)
#define STAGE_BYTES 49152u
template<int EPI>
__global__ __launch_bounds__(256, 1)
void gemm_tc(const float* __restrict__ A, const float* __restrict__ Bw,
             const float* __restrict__ bias, const float* __restrict__ res,
             float* __restrict__ out, int M, int N, int K) {
    extern __shared__ float smem[];            // 3 stages x (A 16KB | B 32KB) = 144 KB

    const int tid  = threadIdx.x;
    const int lane = tid & 31;
    const int w    = tid >> 5;
    const int wm   = w & 1, wn = w >> 1;
    const int mw0  = wm * 64, nw0 = wn * 64;
    const int bx   = blockIdx.x, by = blockIdx.y;
    const int g    = lane >> 2;
    const int tk   = lane & 3;

    // cp.async producer mapping: A row rowL (half colL), B rows rowL and rowL+128
    const int rowL = tid >> 1;                 // 0..127
    const int colL = (tid & 1) * 16;           // 0 or 16
    const float* AptG  = A  + (size_t)(by * 128 + rowL) * K + colL;
    const float* BptG0 = Bw + (size_t)(bx * 256 + rowL) * K + colL;
    const float* BptG1 = Bw + (size_t)(bx * 256 + rowL + 128) * K + colL;
    const uint32_t sbase = (uint32_t)__cvta_generic_to_shared(smem);
    const int sw = rowL & 7;                   // (rowL+128)&7 == sw too
    const uint32_t dstA0 = sbase + (uint32_t)(rowL * 32) * 4u;              // A: 16 KB
    const uint32_t dstB0 = sbase + 16384u + (uint32_t)(rowL * 32) * 4u;     // B: 32 KB

    // ldmatrix consumer mapping
    const int rsel = lane & 7;
    const int tsel = lane >> 3;
    const int rA   = mw0 + ((tsel & 1) << 3) + rsel;    // A: tiles {row-half, k-group}
    const int kA   = tsel >> 1;
    const int rB   = nw0 + ((tsel >> 1) << 3) + rsel;   // B: tiles {j-pair, k-group}
    const int kB   = tsel & 1;

#define CPA(S, KT)                                                            \
    do {                                                                      \
        const uint32_t stoff = (uint32_t)(S) * STAGE_BYTES;                   \
        const uint32_t da  = dstA0 + stoff;                                   \
        const uint32_t db  = dstB0 + stoff;                                   \
        _Pragma("unroll")                                                     \
        for (int f = 0; f < 4; f++) {                                         \
            const int k4 = (colL >> 2) + f;                                   \
            const uint32_t off = (uint32_t)((k4 ^ sw) << 2) * 4u;             \
            CP16(da + off,           AptG  + (KT) + f * 4);                   \
            CP16(db + off,           BptG0 + (KT) + f * 4);                   \
            CP16(db + off + 16384u,  BptG1 + (KT) + f * 4);                   \
        }                                                                     \
        CPCOMMIT();                                                           \
    } while (0)

#define COMPUTE_KS(KS)                                                        \
    do {                                                                      \
        const uint32_t axor = (uint32_t)(((((KS) << 1) | kA) ^ rsel) << 4);   \
        const uint32_t bxor = (uint32_t)(((((KS) << 1) | kB) ^ rsel) << 4);   \
        uint32_t bq[16];                                                      \
        ldsm_x4(bq,      sBst + (uint32_t)(rB * 128) + bxor);                 \
        ldsm_x4(bq + 4,  sBst + (uint32_t)((rB + 16) * 128) + bxor);          \
        ldsm_x4(bq + 8,  sBst + (uint32_t)((rB + 32) * 128) + bxor);          \
        ldsm_x4(bq + 12, sBst + (uint32_t)((rB + 48) * 128) + bxor);          \
        _Pragma("unroll")                                                     \
        for (int i = 0; i < 4; i++) {                                         \
            uint32_t af[4];                                                   \
            ldsm_x4(af, sAst + (uint32_t)((rA + 16 * i) * 128) + axor);       \
            _Pragma("unroll")                                                 \
            for (int j = 0; j < 8; j++) mma8(acc[i][j], af, bq + 2 * j);      \
        }                                                                     \
    } while (0)

    float acc[4][8][4];
#pragma unroll
    for (int i = 0; i < 4; i++)
#pragma unroll
        for (int j = 0; j < 8; j++)
#pragma unroll
            for (int q = 0; q < 4; q++) acc[i][j][q] = 0.f;

    // prologue: 2 stages in flight
    CPA(0, 0);
    CPA(1, 32);

    const int T = K >> 5;
    for (int t = 0; t < T; t++) {
        const int st = t % 3;
        CPWAIT1();
        __syncthreads();
        if (t + 2 < T) {
            CPA((t + 2) % 3, (t + 2) * 32);
        } else {
            CPCOMMIT();
        }
        const uint32_t sAst = sbase + (uint32_t)st * STAGE_BYTES;
        const uint32_t sBst = sAst + 16384u;
        COMPUTE_KS(0);
        COMPUTE_KS(1);
        COMPUTE_KS(2);
        COMPUTE_KS(3);
    }
#undef CPA
#undef COMPUTE_KS

    // ---------------- epilogue ----------------
    const int r_base = by * 128 + mw0 + g;
    const int c_base = bx * 256 + nw0 + 2 * tk;
#pragma unroll
    for (int j = 0; j < 8; j++) {
        const int c0 = c_base + j * 8;
        const float bv0 = bias[c0], bv1 = bias[c0 + 1];
#pragma unroll
        for (int i = 0; i < 4; i++) {
#pragma unroll
            for (int rr = 0; rr < 2; rr++) {
                const int m = r_base + i * 16 + rr * 8;
                float v0 = acc[i][j][rr * 2 + 0] + bv0;
                float v1 = acc[i][j][rr * 2 + 1] + bv1;
                if (EPI == 2 || EPI == 4) {
                    const float2 rv = *(const float2*)(res + (size_t)m * N + c0);
                    v0 += rv.x; v1 += rv.y;
                }
                if (EPI == 3) { v0 = fmaxf(v0, 0.f); v1 = fmaxf(v1, 0.f); }
                float2 t2; t2.x = v0; t2.y = v1;
                if (EPI == 1) {
                    const int h = c0 >> 6, d = c0 & 63;
                    const int b = m >> 10, n = m & 1023;
                    *(float2*)(out + (((size_t)(b * HH + h) * NTOK + n) * DD + d)) = t2;
                } else {
                    *(float2*)(out + (size_t)m * N + c0) = t2;
                }
            }
        }
    }
}

// ---------------- tensor-core flash attention (unchanged from R8) ----------------
#define KS_STRIDE 68
#define VS_STRIDE 132
#define ATT_SMEM ((128 * KS_STRIDE + 64 * VS_STRIDE) * 4)

__global__ __launch_bounds__(256, 1)
void attn_tc(const float* __restrict__ Q, const float* __restrict__ Kg,
             const float* __restrict__ Vg, float* __restrict__ O) {
    extern __shared__ float smem[];
    float* Ks = smem;
    float* Vs = smem + 128 * KS_STRIDE;

    const int tid  = threadIdx.x;
    const int lane = tid & 31;
    const int w    = tid >> 5;
    const int g    = lane >> 2;
    const int tk   = lane & 3;
    const int bh   = blockIdx.y;
    const int qt   = blockIdx.x;
    const int b    = bh >> 2, h = bh & 3;
    const size_t hoff = (size_t)bh * NTOK * DD;
    const float* Qh = Q  + hoff;
    const float* Kh = Kg + hoff;
    const float* Vh = Vg + hoff;
    const int q0 = qt * 128;

    float4 kst[8], vst[8];

#define AFETCH(KT)                                                              \
    do {                                                                        \
        _Pragma("unroll")                                                       \
        for (int i = 0; i < 8; i++) {                                           \
            const int lin = tid + 256 * i;                                      \
            const int kr = lin >> 4, c4 = lin & 15;                             \
            kst[i] = *(const float4*)(Kh + (size_t)((KT) + kr) * DD + c4 * 4);  \
            const int vc4 = lin >> 7, vk = lin & 127;                           \
            vst[i] = *(const float4*)(Vh + (size_t)((KT) + vk) * DD + vc4 * 4); \
        }                                                                       \
    } while (0)

#define ASTORE()                                                                \
    do {                                                                        \
        _Pragma("unroll")                                                       \
        for (int i = 0; i < 8; i++) {                                           \
            const int lin = tid + 256 * i;                                      \
            const int kr = lin >> 4, c4 = lin & 15;                             \
            uint4 t4; t4.x = f2tf(kst[i].x); t4.y = f2tf(kst[i].y);             \
                      t4.z = f2tf(kst[i].z); t4.w = f2tf(kst[i].w);             \
            *(uint4*)(Ks + kr * KS_STRIDE + c4 * 4) = t4;                       \
            const int vc4 = lin >> 7, vk = lin & 127;                           \
            Vs[(vc4 * 4 + 0) * VS_STRIDE + vk] = __uint_as_float(f2tf(vst[i].x)); \
            Vs[(vc4 * 4 + 1) * VS_STRIDE + vk] = __uint_as_float(f2tf(vst[i].y)); \
            Vs[(vc4 * 4 + 2) * VS_STRIDE + vk] = __uint_as_float(f2tf(vst[i].z)); \
            Vs[(vc4 * 4 + 3) * VS_STRIDE + vk] = __uint_as_float(f2tf(vst[i].w)); \
        }                                                                       \
    } while (0)

    AFETCH(0);

#pragma unroll
    for (int i = 0; i < 8; i++) {
        const int lin = tid + 256 * i;
        const int r = lin >> 4, c4 = lin & 15;
        float4 qv = *(const float4*)(Qh + (size_t)(q0 + r) * DD + c4 * 4);
        uint4 t4;
        t4.x = f2tf(qv.x * 0.125f); t4.y = f2tf(qv.y * 0.125f);
        t4.z = f2tf(qv.z * 0.125f); t4.w = f2tf(qv.w * 0.125f);
        *(uint4*)(Ks + r * KS_STRIDE + c4 * 4) = t4;
    }
    __syncthreads();

    uint32_t qa[8][4];
    {
        const float* qr0 = Ks + (w * 16 + g) * KS_STRIDE;
        const float* qr1 = qr0 + 8 * KS_STRIDE;
#pragma unroll
        for (int ks = 0; ks < 8; ks++) {
            qa[ks][0] = __float_as_uint(qr0[ks * 8 + tk]);
            qa[ks][1] = __float_as_uint(qr1[ks * 8 + tk]);
            qa[ks][2] = __float_as_uint(qr0[ks * 8 + tk + 4]);
            qa[ks][3] = __float_as_uint(qr1[ks * 8 + tk + 4]);
        }
    }

    float oacc[8][4];
#pragma unroll
    for (int n = 0; n < 8; n++)
#pragma unroll
        for (int q = 0; q < 4; q++) oacc[n][q] = 0.f;
    float m_g = -INFINITY, m_h = -INFINITY, l_g = 0.f, l_h = 0.f;

    const int src0 = (lane & 28) | (tk >> 1);
    const int src1 = src0 + 2;
    const bool odd = (tk & 1);

#pragma unroll 1
    for (int kt8 = 0; kt8 < 8; kt8++) {
        __syncthreads();
        ASTORE();
        __syncthreads();
        if (kt8 < 7) AFETCH((kt8 + 1) * 128);

        float sacc[16][4];
#pragma unroll
        for (int j = 0; j < 16; j++)
#pragma unroll
            for (int q = 0; q < 4; q++) sacc[j][q] = 0.f;

#pragma unroll
        for (int j = 0; j < 16; j++) {
            const float* krow = Ks + (j * 8 + g) * KS_STRIDE;
#pragma unroll
            for (int ks = 0; ks < 8; ks++) {
                uint32_t kb[2];
                kb[0] = __float_as_uint(krow[ks * 8 + tk]);
                kb[1] = __float_as_uint(krow[ks * 8 + tk + 4]);
                mma8(sacc[j], qa[ks], kb);
            }
        }

        float tg = -INFINITY, th = -INFINITY;
#pragma unroll
        for (int j = 0; j < 16; j++) {
            tg = fmaxf(tg, fmaxf(sacc[j][0], sacc[j][1]));
            th = fmaxf(th, fmaxf(sacc[j][2], sacc[j][3]));
        }
        tg = fmaxf(tg, __shfl_xor_sync(0xffffffffu, tg, 1));
        tg = fmaxf(tg, __shfl_xor_sync(0xffffffffu, tg, 2));
        th = fmaxf(th, __shfl_xor_sync(0xffffffffu, th, 1));
        th = fmaxf(th, __shfl_xor_sync(0xffffffffu, th, 2));
        const float mg_new = fmaxf(m_g, tg);
        const float mh_new = fmaxf(m_h, th);
        const float cg = __expf(m_g - mg_new);
        const float ch = __expf(m_h - mh_new);
        m_g = mg_new; m_h = mh_new;
        l_g *= cg; l_h *= ch;
#pragma unroll
        for (int n = 0; n < 8; n++) {
            oacc[n][0] *= cg; oacc[n][1] *= cg;
            oacc[n][2] *= ch; oacc[n][3] *= ch;
        }
#pragma unroll
        for (int j = 0; j < 16; j++) {
            const float p0 = __expf(sacc[j][0] - m_g);
            const float p1 = __expf(sacc[j][1] - m_g);
            const float p2 = __expf(sacc[j][2] - m_h);
            const float p3 = __expf(sacc[j][3] - m_h);
            l_g += p0 + p1;  l_h += p2 + p3;
            sacc[j][0] = __uint_as_float(f2tf(p0));
            sacc[j][1] = __uint_as_float(f2tf(p1));
            sacc[j][2] = __uint_as_float(f2tf(p2));
            sacc[j][3] = __uint_as_float(f2tf(p3));
        }

#pragma unroll
        for (int ks = 0; ks < 16; ks++) {
            const float e00 = __shfl_sync(0xffffffffu, sacc[ks][0], src0);
            const float e01 = __shfl_sync(0xffffffffu, sacc[ks][1], src0);
            const float e10 = __shfl_sync(0xffffffffu, sacc[ks][2], src0);
            const float e11 = __shfl_sync(0xffffffffu, sacc[ks][3], src0);
            const float f00 = __shfl_sync(0xffffffffu, sacc[ks][0], src1);
            const float f01 = __shfl_sync(0xffffffffu, sacc[ks][1], src1);
            const float f10 = __shfl_sync(0xffffffffu, sacc[ks][2], src1);
            const float f11 = __shfl_sync(0xffffffffu, sacc[ks][3], src1);
            uint32_t pa[4];
            pa[0] = __float_as_uint(odd ? e01 : e00);
            pa[1] = __float_as_uint(odd ? e11 : e10);
            pa[2] = __float_as_uint(odd ? f01 : f00);
            pa[3] = __float_as_uint(odd ? f11 : f10);
#pragma unroll
            for (int n = 0; n < 8; n++) {
                const float* vr = Vs + (n * 8 + g) * VS_STRIDE + ks * 8;
                uint32_t vb[2];
                vb[0] = __float_as_uint(vr[tk]);
                vb[1] = __float_as_uint(vr[tk + 4]);
                mma8(oacc[n], pa, vb);
            }
        }
    }
#undef AFETCH
#undef ASTORE

    l_g += __shfl_xor_sync(0xffffffffu, l_g, 1);
    l_g += __shfl_xor_sync(0xffffffffu, l_g, 2);
    l_h += __shfl_xor_sync(0xffffffffu, l_h, 1);
    l_h += __shfl_xor_sync(0xffffffffu, l_h, 2);
    const float ig = 1.f / l_g;
    const float ih = 1.f / l_h;

    const int rg = b * NTOK + q0 + w * 16 + g;
    const int cbase = h * DD + 2 * tk;
#pragma unroll
    for (int n = 0; n < 8; n++) {
        float2 t0; t0.x = oacc[n][0] * ig; t0.y = oacc[n][1] * ig;
        *(float2*)(O + (size_t)rg * CCH + cbase + n * 8) = t0;
        float2 t1; t1.x = oacc[n][2] * ih; t1.y = oacc[n][3] * ih;
        *(float2*)(O + (size_t)(rg + 8) * CCH + cbase + n * 8) = t1;
    }
}

// ---------------- host launcher ----------------
extern "C" void kernel_launch(void* const* d_in, const int* in_sizes, int n_in,
                              void* d_out, int out_size) {
    const float* x     = (const float*)d_in[0];
    const float* wq    = (const float*)d_in[1];
    const float* bq    = (const float*)d_in[2];
    const float* wk    = (const float*)d_in[3];
    const float* bk    = (const float*)d_in[4];
    const float* wv    = (const float*)d_in[5];
    const float* bv    = (const float*)d_in[6];
    const float* wo    = (const float*)d_in[7];
    const float* bo    = (const float*)d_in[8];
    const float* g1    = (const float*)d_in[9];
    const float* beta1 = (const float*)d_in[10];
    const float* g2    = (const float*)d_in[11];
    const float* beta2 = (const float*)d_in[12];
    const float* w1    = (const float*)d_in[13];
    const float* bf1   = (const float*)d_in[14];
    const float* w2    = (const float*)d_in[15];
    const float* bf2   = (const float*)d_in[16];

    float *XNp, *H2p, *Qp, *Kp, *Vp, *AOp, *R1p, *MIDp;
    cudaGetSymbolAddress((void**)&XNp,  g_XN);
    cudaGetSymbolAddress((void**)&H2p,  g_H2);
    cudaGetSymbolAddress((void**)&Qp,   g_Q);
    cudaGetSymbolAddress((void**)&Kp,   g_K);
    cudaGetSymbolAddress((void**)&Vp,   g_V);
    cudaGetSymbolAddress((void**)&AOp,  g_AO);
    cudaGetSymbolAddress((void**)&R1p,  g_R1);
    cudaGetSymbolAddress((void**)&MIDp, g_MID);

    const int SMEM = 147456;   // 3 stages x 48 KB
    cudaFuncSetAttribute(gemm_tc<1>, cudaFuncAttributeMaxDynamicSharedMemorySize, SMEM);
    cudaFuncSetAttribute(gemm_tc<2>, cudaFuncAttributeMaxDynamicSharedMemorySize, SMEM);
    cudaFuncSetAttribute(gemm_tc<3>, cudaFuncAttributeMaxDynamicSharedMemorySize, SMEM);
    cudaFuncSetAttribute(gemm_tc<4>, cudaFuncAttributeMaxDynamicSharedMemorySize, SMEM);
    cudaFuncSetAttribute(attn_tc,    cudaFuncAttributeMaxDynamicSharedMemorySize, ATT_SMEM);

    const int NRM_GRID = (MROWS * CCH / 4) / 256;   // 8192

    // BN1: stats -> finalize -> normalize x
    zero_acc_kernel<<<1, 1024>>>();
    bn_stats_kernel<<<256, 256>>>(x, 0);
    bn_finalize_kernel<<<1, 256>>>(g1, beta1, 0);
    normalize_kernel<<<NRM_GRID, 256>>>(x, XNp, 0);

    // QKV projections, outputs in (B,H,N,D)
    gemm_tc<1><<<dim3(1, 256), 256, SMEM>>>(XNp, wq, bq, nullptr, Qp, MROWS, CCH, CCH);
    gemm_tc<1><<<dim3(1, 256), 256, SMEM>>>(XNp, wk, bk, nullptr, Kp, MROWS, CCH, CCH);
    gemm_tc<1><<<dim3(1, 256), 256, SMEM>>>(XNp, wv, bv, nullptr, Vp, MROWS, CCH, CCH);

    // attention (tensor-core flash)
    attn_tc<<<dim3(NTOK / 128, BB * HH), 256, ATT_SMEM>>>(Qp, Kp, Vp, AOp);

    // O projection + residual, then BN2 stats over R1 -> normalize -> H2
    gemm_tc<2><<<dim3(1, 256), 256, SMEM>>>(AOp, wo, bo, x, R1p, MROWS, CCH, CCH);
    bn_stats_kernel<<<256, 256>>>(R1p, 512);
    bn_finalize_kernel<<<1, 256>>>(g2, beta2, 1);
    normalize_kernel<<<NRM_GRID, 256>>>(R1p, H2p, 1);

    // MLP
    gemm_tc<3><<<dim3(4, 256), 256, SMEM>>>(H2p, w1, bf1, nullptr, MIDp, MROWS, FF, CCH);
    gemm_tc<4><<<dim3(1, 256), 256, SMEM>>>(MIDp, w2, bf2, R1p, (float*)d_out, MROWS, CCH, FF);
}

// round 15
// speedup vs baseline: 1.0283x; 1.0283x over previous
#include <cuda_runtime.h>
#include <math.h>
#include <stdint.h>

#define BB   32
#define NTOK 1024
#define CCH  256
#define HH   4
#define DD   64
#define FF   1024
#define MROWS (BB * NTOK)   // 32768
#define EPSV 1e-5f

// ---------------- static device scratch ----------------
__device__ float g_acc[1024];
__device__ float g_scale1[CCH], g_shift1[CCH];
__device__ float g_scale2[CCH], g_shift2[CCH];
__device__ float g_XN [(size_t)MROWS * CCH];  // BN1-normalized x
__device__ float g_H2 [(size_t)MROWS * CCH];  // BN2-normalized R1
__device__ float g_Q  [(size_t)MROWS * CCH];  // (B,H,N,D)
__device__ float g_K  [(size_t)MROWS * CCH];
__device__ float g_V  [(size_t)MROWS * CCH];
__device__ float g_AO [(size_t)MROWS * CCH];
__device__ float g_R1 [(size_t)MROWS * CCH];
__device__ float g_MID[(size_t)MROWS * FF];

// ---------------- small kernels ----------------
__global__ void zero_acc_kernel() {
    g_acc[threadIdx.x] = 0.f;
}

__global__ void bn_stats_kernel(const float* __restrict__ x) {
    int c  = threadIdx.x;
    int r0 = blockIdx.x * 128;
    const float* p = x + (size_t)r0 * CCH + c;
    float s = 0.f, q = 0.f;
#pragma unroll 4
    for (int i = 0; i < 128; i++) {
        float v = p[(size_t)i * CCH];
        s += v;
        q += v * v;
    }
    atomicAdd(&g_acc[c],        s);
    atomicAdd(&g_acc[CCH + c],  q);
}

__global__ void bn_finalize_kernel(const float* __restrict__ g,
                                   const float* __restrict__ beta, int which) {
    int c = threadIdx.x;
    float invn = 1.f / (float)MROWS;
    float mean = g_acc[which * 512 + c] * invn;
    float var  = g_acc[which * 512 + 256 + c] * invn - mean * mean;
    float sc   = g[c] * rsqrtf(var + EPSV);
    float sh   = beta[c] - mean * sc;
    if (which == 0) { g_scale1[c] = sc; g_shift1[c] = sh; }
    else            { g_scale2[c] = sc; g_shift2[c] = sh; }
}

__global__ __launch_bounds__(256)
void normalize_kernel(const float* __restrict__ in, float* __restrict__ out, int which) {
    const int idx = blockIdx.x * 256 + threadIdx.x;
    const int c = (idx * 4) & (CCH - 1);
    const float* sc = which ? g_scale2 : g_scale1;
    const float* sh = which ? g_shift2 : g_shift1;
    float4 v = ((const float4*)in)[idx];
    float4 o;
    o.x = v.x * sc[c]     + sh[c];
    o.y = v.y * sc[c + 1] + sh[c + 1];
    o.z = v.z * sc[c + 2] + sh[c + 2];
    o.w = v.w * sc[c + 3] + sh[c + 3];
    ((float4*)out)[idx] = o;
}

// ---------------- tf32 helpers ----------------
__device__ __forceinline__ uint32_t f2tf(float x) {
    uint32_t r;
    asm("cvt.rna.tf32.f32 %0, %1;" : "=r"(r) : "f"(x));
    return r;
}

__device__ __forceinline__ void mma8(float* c, const uint32_t* a, const uint32_t* b) {
    asm volatile(
        "mma.sync.aligned.m16n8k8.row.col.f32.tf32.tf32.f32 "
        "{%0,%1,%2,%3}, {%4,%5,%6,%7}, {%8,%9}, {%0,%1,%2,%3};"
        : "+f"(c[0]), "+f"(c[1]), "+f"(c[2]), "+f"(c[3])
        : "r"(a[0]), "r"(a[1]), "r"(a[2]), "r"(a[3]), "r"(b[0]), "r"(b[1]));
}

__device__ __forceinline__ void ldsm_x4(uint32_t* r, uint32_t addr) {
    asm volatile("ldmatrix.sync.aligned.m8n8.x4.shared.b16 {%0,%1,%2,%3}, [%4];"
                 : "=r"(r[0]), "=r"(r[1]), "=r"(r[2]), "=r"(r[3]) : "r"(addr));
}

#define CP16(dst, src) \
    asm volatile("cp.async.cg.shared.global [%0], [%1], 16;" :: "r"(dst), "l"(src))
#define CPCOMMIT() asm volatile("cp.async.commit_group;")
#define CPWAIT1()  asm volatile("cp.async.wait_group 1;")

// ---------------- tf32 tensor-core NT GEMM (EXACT R8 structure) ----------------
// EPI: 2 = +bias+res, store, BN2 stats   3 = +bias, ReLU   4 = +bias+res (final out)
template<int EPI>
__global__ __launch_bounds__(256, 2)
void gemm_tc(const float* __restrict__ A, const float* __restrict__ Bw,
             const float* __restrict__ bias, const float* __restrict__ res,
             float* __restrict__ out, int M, int N, int K) {
    extern __shared__ float smem[];            // 3 stages x (A 16KB | B 16KB) = 96 KB
    __shared__ float ssum[128];
    __shared__ float ssq[128];

    const int tid  = threadIdx.x;
    const int lane = tid & 31;
    const int w    = tid >> 5;
    const int g    = lane >> 2;
    const int tk   = lane & 3;
    const int wm   = w & 1, wn = w >> 1;
    const int mw0  = wm * 64, nw0 = wn * 32;
    const int bx   = blockIdx.x, by = blockIdx.y;

    if (EPI == 2 && tid < 128) { ssum[tid] = 0.f; ssq[tid] = 0.f; }

    const int rowL = tid >> 1;
    const int colL = (tid & 1) * 16;
    const float* AptG = A  + (size_t)(by * 128 + rowL) * K + colL;
    const float* BptG = Bw + (size_t)(bx * 128 + rowL) * K + colL;
    const uint32_t sbase = (uint32_t)__cvta_generic_to_shared(smem);
    const int sw = rowL & 7;
    const uint32_t dstA0 = sbase + (uint32_t)(rowL * 32) * 4u;

    const int rsel = lane & 7;
    const int tsel = lane >> 3;
    const int rA   = mw0 + ((tsel & 1) << 3) + rsel;
    const int kA   = tsel >> 1;
    const int rB   = nw0 + ((tsel >> 1) << 3) + rsel;
    const int kB   = tsel & 1;

#define CPA(S, KT)                                                            \
    do {                                                                      \
        const uint32_t da = dstA0 + (uint32_t)(S) * 32768u;                   \
        _Pragma("unroll")                                                     \
        for (int f = 0; f < 4; f++) {                                         \
            const int k4 = (colL >> 2) + f;                                   \
            const uint32_t off = (uint32_t)((k4 ^ sw) << 2) * 4u;             \
            CP16(da + off,          AptG + (KT) + f * 4);                     \
            CP16(da + off + 16384u, BptG + (KT) + f * 4);                     \
        }                                                                     \
        CPCOMMIT();                                                           \
    } while (0)

#define COMPUTE_KS(KS)                                                        \
    do {                                                                      \
        const uint32_t axor = (uint32_t)(((((KS) << 1) | kA) ^ rsel) << 4);   \
        const uint32_t bxor = (uint32_t)(((((KS) << 1) | kB) ^ rsel) << 4);   \
        uint32_t bq[8];                                                       \
        ldsm_x4(bq,     sBst + (uint32_t)(rB * 128) + bxor);                  \
        ldsm_x4(bq + 4, sBst + (uint32_t)((rB + 16) * 128) + bxor);           \
        _Pragma("unroll")                                                     \
        for (int i = 0; i < 4; i++) {                                         \
            uint32_t af[4];                                                   \
            ldsm_x4(af, sAst + (uint32_t)((rA + 16 * i) * 128) + axor);       \
            mma8(acc[i][0], af, bq);                                          \
            mma8(acc[i][1], af, bq + 2);                                      \
            mma8(acc[i][2], af, bq + 4);                                      \
            mma8(acc[i][3], af, bq + 6);                                      \
        }                                                                     \
    } while (0)

    float acc[4][4][4];
#pragma unroll
    for (int i = 0; i < 4; i++)
#pragma unroll
        for (int j = 0; j < 4; j++)
#pragma unroll
            for (int q = 0; q < 4; q++) acc[i][j][q] = 0.f;

    CPA(0, 0);
    CPA(1, 32);

    const int T = K >> 5;
    int st = 0;
    for (int t = 0; t < T; t++) {
        CPWAIT1();
        __syncthreads();
        if (t + 2 < T) {
            const int s2 = (st == 0) ? 2 : st - 1;
            CPA(s2, (t + 2) * 32);
        } else {
            CPCOMMIT();
        }
        const uint32_t sAst = sbase + (uint32_t)st * 32768u;
        const uint32_t sBst = sAst + 16384u;
        COMPUTE_KS(0);
        COMPUTE_KS(1);
        COMPUTE_KS(2);
        COMPUTE_KS(3);
        st = (st == 2) ? 0 : st + 1;
    }
#undef CPA
#undef COMPUTE_KS

    const int r_base = by * 128 + mw0 + g;
    const int c_glob = bx * 128 + nw0 + 2 * tk;
#pragma unroll
    for (int j = 0; j < 4; j++) {
        const int c0 = c_glob + j * 8;
        const float bv0 = bias[c0], bv1 = bias[c0 + 1];
        float cs0 = 0.f, cq0 = 0.f, cs1 = 0.f, cq1 = 0.f;
#pragma unroll
        for (int i = 0; i < 4; i++) {
#pragma unroll
            for (int rr = 0; rr < 2; rr++) {
                const int m = r_base + i * 16 + rr * 8;
                float v0 = acc[i][j][rr * 2 + 0] + bv0;
                float v1 = acc[i][j][rr * 2 + 1] + bv1;
                if (EPI == 2 || EPI == 4) {
                    const float2 rv = *(const float2*)(res + (size_t)m * N + c0);
                    v0 += rv.x; v1 += rv.y;
                }
                if (EPI == 3) { v0 = fmaxf(v0, 0.f); v1 = fmaxf(v1, 0.f); }
                float2 t2; t2.x = v0; t2.y = v1;
                *(float2*)(out + (size_t)m * N + c0) = t2;
                if (EPI == 2) { cs0 += v0; cq0 += v0 * v0; cs1 += v1; cq1 += v1 * v1; }
            }
        }
        if (EPI == 2) {
            const int lc = nw0 + j * 8 + 2 * tk;
            atomicAdd(&ssum[lc],     cs0); atomicAdd(&ssq[lc],     cq0);
            atomicAdd(&ssum[lc + 1], cs1); atomicAdd(&ssq[lc + 1], cq1);
        }
    }
    if (EPI == 2) {
        __syncthreads();
        if (tid < 128) {
            atomicAdd(&g_acc[512 + bx * 128 + tid], ssum[tid]);
            atomicAdd(&g_acc[768 + bx * 128 + tid], ssq[tid]);
        }
    }
}

// ---------------- merged QKV GEMM: blockIdx.z selects {w,b,out}; (B,H,N,D) scatter ----------------
__global__ __launch_bounds__(256, 2)
void gemm_qkv(const float* __restrict__ A,
              const float* __restrict__ w0, const float* __restrict__ w1, const float* __restrict__ w2,
              const float* __restrict__ b0, const float* __restrict__ b1, const float* __restrict__ b2,
              float* __restrict__ o0, float* __restrict__ o1, float* __restrict__ o2) {
    extern __shared__ float smem[];
    const int K = CCH;
    const float* Bw   = (blockIdx.z == 0) ? w0 : (blockIdx.z == 1) ? w1 : w2;
    const float* bias = (blockIdx.z == 0) ? b0 : (blockIdx.z == 1) ? b1 : b2;
    float* out        = (blockIdx.z == 0) ? o0 : (blockIdx.z == 1) ? o1 : o2;

    const int tid  = threadIdx.x;
    const int lane = tid & 31;
    const int w    = tid >> 5;
    const int g    = lane >> 2;
    const int tk   = lane & 3;
    const int wm   = w & 1, wn = w >> 1;
    const int mw0  = wm * 64, nw0 = wn * 32;
    const int bx   = blockIdx.x, by = blockIdx.y;

    const int rowL = tid >> 1;
    const int colL = (tid & 1) * 16;
    const float* AptG = A  + (size_t)(by * 128 + rowL) * K + colL;
    const float* BptG = Bw + (size_t)(bx * 128 + rowL) * K + colL;
    const uint32_t sbase = (uint32_t)__cvta_generic_to_shared(smem);
    const int sw = rowL & 7;
    const uint32_t dstA0 = sbase + (uint32_t)(rowL * 32) * 4u;

    const int rsel = lane & 7;
    const int tsel = lane >> 3;
    const int rA   = mw0 + ((tsel & 1) << 3) + rsel;
    const int kA   = tsel >> 1;
    const int rB   = nw0 + ((tsel >> 1) << 3) + rsel;
    const int kB   = tsel & 1;

#define CPA(S, KT)                                                            \
    do {                                                                      \
        const uint32_t da = dstA0 + (uint32_t)(S) * 32768u;                   \
        _Pragma("unroll")                                                     \
        for (int f = 0; f < 4; f++) {                                         \
            const int k4 = (colL >> 2) + f;                                   \
            const uint32_t off = (uint32_t)((k4 ^ sw) << 2) * 4u;             \
            CP16(da + off,          AptG + (KT) + f * 4);                     \
            CP16(da + off + 16384u, BptG + (KT) + f * 4);                     \
        }                                                                     \
        CPCOMMIT();                                                           \
    } while (0)

#define COMPUTE_KS(KS)                                                        \
    do {                                                                      \
        const uint32_t axor = (uint32_t)(((((KS) << 1) | kA) ^ rsel) << 4);   \
        const uint32_t bxor = (uint32_t)(((((KS) << 1) | kB) ^ rsel) << 4);   \
        uint32_t bq[8];                                                       \
        ldsm_x4(bq,     sBst + (uint32_t)(rB * 128) + bxor);                  \
        ldsm_x4(bq + 4, sBst + (uint32_t)((rB + 16) * 128) + bxor);           \
        _Pragma("unroll")                                                     \
        for (int i = 0; i < 4; i++) {                                         \
            uint32_t af[4];                                                   \
            ldsm_x4(af, sAst + (uint32_t)((rA + 16 * i) * 128) + axor);       \
            mma8(acc[i][0], af, bq);                                          \
            mma8(acc[i][1], af, bq + 2);                                      \
            mma8(acc[i][2], af, bq + 4);                                      \
            mma8(acc[i][3], af, bq + 6);                                      \
        }                                                                     \
    } while (0)

    float acc[4][4][4];
#pragma unroll
    for (int i = 0; i < 4; i++)
#pragma unroll
        for (int j = 0; j < 4; j++)
#pragma unroll
            for (int q = 0; q < 4; q++) acc[i][j][q] = 0.f;

    CPA(0, 0);
    CPA(1, 32);

    const int T = K >> 5;   // 8
    int st = 0;
    for (int t = 0; t < T; t++) {
        CPWAIT1();
        __syncthreads();
        if (t + 2 < T) {
            const int s2 = (st == 0) ? 2 : st - 1;
            CPA(s2, (t + 2) * 32);
        } else {
            CPCOMMIT();
        }
        const uint32_t sAst = sbase + (uint32_t)st * 32768u;
        const uint32_t sBst = sAst + 16384u;
        COMPUTE_KS(0);
        COMPUTE_KS(1);
        COMPUTE_KS(2);
        COMPUTE_KS(3);
        st = (st == 2) ? 0 : st + 1;
    }
#undef CPA
#undef COMPUTE_KS

    const int r_base = by * 128 + mw0 + g;
    const int c_glob = bx * 128 + nw0 + 2 * tk;
#pragma unroll
    for (int j = 0; j < 4; j++) {
        const int c0 = c_glob + j * 8;
        const float bv0 = bias[c0], bv1 = bias[c0 + 1];
#pragma unroll
        for (int i = 0; i < 4; i++) {
#pragma unroll
            for (int rr = 0; rr < 2; rr++) {
                const int m = r_base + i * 16 + rr * 8;
                float2 t2;
                t2.x = acc[i][j][rr * 2 + 0] + bv0;
                t2.y = acc[i][j][rr * 2 + 1] + bv1;
                const int h = c0 >> 6, d = c0 & 63;
                const int b = m >> 10, n = m & 1023;
                *(float2*)(out + (((size_t)(b * HH + h) * NTOK + n) * DD + d)) = t2;
            }
        }
    }
}

// ---------------- tensor-core flash attention (EXACT R8 version) ----------------
#define KS_STRIDE 68
#define VS_STRIDE 132
#define ATT_SMEM ((128 * KS_STRIDE + 64 * VS_STRIDE) * 4)

__global__ __launch_bounds__(256, 1)
void attn_tc(const float* __restrict__ Q, const float* __restrict__ Kg,
             const float* __restrict__ Vg, float* __restrict__ O) {
    extern __shared__ float smem[];
    float* Ks = smem;
    float* Vs = smem + 128 * KS_STRIDE;

    const int tid  = threadIdx.x;
    const int lane = tid & 31;
    const int w    = tid >> 5;
    const int g    = lane >> 2;
    const int tk   = lane & 3;
    const int bh   = blockIdx.y;
    const int qt   = blockIdx.x;
    const int b    = bh >> 2, h = bh & 3;
    const size_t hoff = (size_t)bh * NTOK * DD;
    const float* Qh = Q  + hoff;
    const float* Kh = Kg + hoff;
    const float* Vh = Vg + hoff;
    const int q0 = qt * 128;

    float4 kst[8], vst[8];

#define AFETCH(KT)                                                              \
    do {                                                                        \
        _Pragma("unroll")                                                       \
        for (int i = 0; i < 8; i++) {                                           \
            const int lin = tid + 256 * i;                                      \
            const int kr = lin >> 4, c4 = lin & 15;                             \
            kst[i] = *(const float4*)(Kh + (size_t)((KT) + kr) * DD + c4 * 4);  \
            const int vc4 = lin >> 7, vk = lin & 127;                           \
            vst[i] = *(const float4*)(Vh + (size_t)((KT) + vk) * DD + vc4 * 4); \
        }                                                                       \
    } while (0)

#define ASTORE()                                                                \
    do {                                                                        \
        _Pragma("unroll")                                                       \
        for (int i = 0; i < 8; i++) {                                           \
            const int lin = tid + 256 * i;                                      \
            const int kr = lin >> 4, c4 = lin & 15;                             \
            uint4 t4; t4.x = f2tf(kst[i].x); t4.y = f2tf(kst[i].y);             \
                      t4.z = f2tf(kst[i].z); t4.w = f2tf(kst[i].w);             \
            *(uint4*)(Ks + kr * KS_STRIDE + c4 * 4) = t4;                       \
            const int vc4 = lin >> 7, vk = lin & 127;                           \
            Vs[(vc4 * 4 + 0) * VS_STRIDE + vk] = __uint_as_float(f2tf(vst[i].x)); \
            Vs[(vc4 * 4 + 1) * VS_STRIDE + vk] = __uint_as_float(f2tf(vst[i].y)); \
            Vs[(vc4 * 4 + 2) * VS_STRIDE + vk] = __uint_as_float(f2tf(vst[i].z)); \
            Vs[(vc4 * 4 + 3) * VS_STRIDE + vk] = __uint_as_float(f2tf(vst[i].w)); \
        }                                                                       \
    } while (0)

    AFETCH(0);

#pragma unroll
    for (int i = 0; i < 8; i++) {
        const int lin = tid + 256 * i;
        const int r = lin >> 4, c4 = lin & 15;
        float4 qv = *(const float4*)(Qh + (size_t)(q0 + r) * DD + c4 * 4);
        uint4 t4;
        t4.x = f2tf(qv.x * 0.125f); t4.y = f2tf(qv.y * 0.125f);
        t4.z = f2tf(qv.z * 0.125f); t4.w = f2tf(qv.w * 0.125f);
        *(uint4*)(Ks + r * KS_STRIDE + c4 * 4) = t4;
    }
    __syncthreads();

    uint32_t qa[8][4];
    {
        const float* qr0 = Ks + (w * 16 + g) * KS_STRIDE;
        const float* qr1 = qr0 + 8 * KS_STRIDE;
#pragma unroll
        for (int ks = 0; ks < 8; ks++) {
            qa[ks][0] = __float_as_uint(qr0[ks * 8 + tk]);
            qa[ks][1] = __float_as_uint(qr1[ks * 8 + tk]);
            qa[ks][2] = __float_as_uint(qr0[ks * 8 + tk + 4]);
            qa[ks][3] = __float_as_uint(qr1[ks * 8 + tk + 4]);
        }
    }

    float oacc[8][4];
#pragma unroll
    for (int n = 0; n < 8; n++)
#pragma unroll
        for (int q = 0; q < 4; q++) oacc[n][q] = 0.f;
    float m_g = -INFINITY, m_h = -INFINITY, l_g = 0.f, l_h = 0.f;

    const int src0 = (lane & 28) | (tk >> 1);
    const int src1 = src0 + 2;
    const bool odd = (tk & 1);

#pragma unroll 1
    for (int kt8 = 0; kt8 < 8; kt8++) {
        __syncthreads();
        ASTORE();
        __syncthreads();
        if (kt8 < 7) AFETCH((kt8 + 1) * 128);

        float sacc[16][4];
#pragma unroll
        for (int j = 0; j < 16; j++)
#pragma unroll
            for (int q = 0; q < 4; q++) sacc[j][q] = 0.f;

#pragma unroll
        for (int j = 0; j < 16; j++) {
            const float* krow = Ks + (j * 8 + g) * KS_STRIDE;
#pragma unroll
            for (int ks = 0; ks < 8; ks++) {
                uint32_t kb[2];
                kb[0] = __float_as_uint(krow[ks * 8 + tk]);
                kb[1] = __float_as_uint(krow[ks * 8 + tk + 4]);
                mma8(sacc[j], qa[ks], kb);
            }
        }

        float tg = -INFINITY, th = -INFINITY;
#pragma unroll
        for (int j = 0; j < 16; j++) {
            tg = fmaxf(tg, fmaxf(sacc[j][0], sacc[j][1]));
            th = fmaxf(th, fmaxf(sacc[j][2], sacc[j][3]));
        }
        tg = fmaxf(tg, __shfl_xor_sync(0xffffffffu, tg, 1));
        tg = fmaxf(tg, __shfl_xor_sync(0xffffffffu, tg, 2));
        th = fmaxf(th, __shfl_xor_sync(0xffffffffu, th, 1));
        th = fmaxf(th, __shfl_xor_sync(0xffffffffu, th, 2));
        const float mg_new = fmaxf(m_g, tg);
        const float mh_new = fmaxf(m_h, th);
        const float cg = __expf(m_g - mg_new);
        const float ch = __expf(m_h - mh_new);
        m_g = mg_new; m_h = mh_new;
        l_g *= cg; l_h *= ch;
#pragma unroll
        for (int n = 0; n < 8; n++) {
            oacc[n][0] *= cg; oacc[n][1] *= cg;
            oacc[n][2] *= ch; oacc[n][3] *= ch;
        }
#pragma unroll
        for (int j = 0; j < 16; j++) {
            const float p0 = __expf(sacc[j][0] - m_g);
            const float p1 = __expf(sacc[j][1] - m_g);
            const float p2 = __expf(sacc[j][2] - m_h);
            const float p3 = __expf(sacc[j][3] - m_h);
            l_g += p0 + p1;  l_h += p2 + p3;
            sacc[j][0] = __uint_as_float(f2tf(p0));
            sacc[j][1] = __uint_as_float(f2tf(p1));
            sacc[j][2] = __uint_as_float(f2tf(p2));
            sacc[j][3] = __uint_as_float(f2tf(p3));
        }

#pragma unroll
        for (int ks = 0; ks < 16; ks++) {
            const float e00 = __shfl_sync(0xffffffffu, sacc[ks][0], src0);
            const float e01 = __shfl_sync(0xffffffffu, sacc[ks][1], src0);
            const float e10 = __shfl_sync(0xffffffffu, sacc[ks][2], src0);
            const float e11 = __shfl_sync(0xffffffffu, sacc[ks][3], src0);
            const float f00 = __shfl_sync(0xffffffffu, sacc[ks][0], src1);
            const float f01 = __shfl_sync(0xffffffffu, sacc[ks][1], src1);
            const float f10 = __shfl_sync(0xffffffffu, sacc[ks][2], src1);
            const float f11 = __shfl_sync(0xffffffffu, sacc[ks][3], src1);
            uint32_t pa[4];
            pa[0] = __float_as_uint(odd ? e01 : e00);
            pa[1] = __float_as_uint(odd ? e11 : e10);
            pa[2] = __float_as_uint(odd ? f01 : f00);
            pa[3] = __float_as_uint(odd ? f11 : f10);
#pragma unroll
            for (int n = 0; n < 8; n++) {
                const float* vr = Vs + (n * 8 + g) * VS_STRIDE + ks * 8;
                uint32_t vb[2];
                vb[0] = __float_as_uint(vr[tk]);
                vb[1] = __float_as_uint(vr[tk + 4]);
                mma8(oacc[n], pa, vb);
            }
        }
    }
#undef AFETCH
#undef ASTORE

    l_g += __shfl_xor_sync(0xffffffffu, l_g, 1);
    l_g += __shfl_xor_sync(0xffffffffu, l_g, 2);
    l_h += __shfl_xor_sync(0xffffffffu, l_h, 1);
    l_h += __shfl_xor_sync(0xffffffffu, l_h, 2);
    const float ig = 1.f / l_g;
    const float ih = 1.f / l_h;

    const int rg = b * NTOK + q0 + w * 16 + g;
    const int cbase = h * DD + 2 * tk;
#pragma unroll
    for (int n = 0; n < 8; n++) {
        float2 t0; t0.x = oacc[n][0] * ig; t0.y = oacc[n][1] * ig;
        *(float2*)(O + (size_t)rg * CCH + cbase + n * 8) = t0;
        float2 t1; t1.x = oacc[n][2] * ih; t1.y = oacc[n][3] * ih;
        *(float2*)(O + (size_t)(rg + 8) * CCH + cbase + n * 8) = t1;
    }
}

// ---------------- host launcher ----------------
extern "C" void kernel_launch(void* const* d_in, const int* in_sizes, int n_in,
                              void* d_out, int out_size) {
    const float* x     = (const float*)d_in[0];
    const float* wq    = (const float*)d_in[1];
    const float* bq    = (const float*)d_in[2];
    const float* wk    = (const float*)d_in[3];
    const float* bk    = (const float*)d_in[4];
    const float* wv    = (const float*)d_in[5];
    const float* bv    = (const float*)d_in[6];
    const float* wo    = (const float*)d_in[7];
    const float* bo    = (const float*)d_in[8];
    const float* g1    = (const float*)d_in[9];
    const float* beta1 = (const float*)d_in[10];
    const float* g2    = (const float*)d_in[11];
    const float* beta2 = (const float*)d_in[12];
    const float* w1    = (const float*)d_in[13];
    const float* bf1   = (const float*)d_in[14];
    const float* w2    = (const float*)d_in[15];
    const float* bf2   = (const float*)d_in[16];

    float *XNp, *H2p, *Qp, *Kp, *Vp, *AOp, *R1p, *MIDp;
    cudaGetSymbolAddress((void**)&XNp,  g_XN);
    cudaGetSymbolAddress((void**)&H2p,  g_H2);
    cudaGetSymbolAddress((void**)&Qp,   g_Q);
    cudaGetSymbolAddress((void**)&Kp,   g_K);
    cudaGetSymbolAddress((void**)&Vp,   g_V);
    cudaGetSymbolAddress((void**)&AOp,  g_AO);
    cudaGetSymbolAddress((void**)&R1p,  g_R1);
    cudaGetSymbolAddress((void**)&MIDp, g_MID);

    const int SMEM = 98304;   // 3 stages x 32 KB
    cudaFuncSetAttribute(gemm_qkv,   cudaFuncAttributeMaxDynamicSharedMemorySize, SMEM);
    cudaFuncSetAttribute(gemm_tc<2>, cudaFuncAttributeMaxDynamicSharedMemorySize, SMEM);
    cudaFuncSetAttribute(gemm_tc<3>, cudaFuncAttributeMaxDynamicSharedMemorySize, SMEM);
    cudaFuncSetAttribute(gemm_tc<4>, cudaFuncAttributeMaxDynamicSharedMemorySize, SMEM);
    cudaFuncSetAttribute(attn_tc,    cudaFuncAttributeMaxDynamicSharedMemorySize, ATT_SMEM);

    const int NRM_GRID = (MROWS * CCH / 4) / 256;   // 8192

    // BN1: stats -> finalize -> normalize x
    zero_acc_kernel<<<1, 1024>>>();
    bn_stats_kernel<<<256, 256>>>(x);
    bn_finalize_kernel<<<1, 256>>>(g1, beta1, 0);
    normalize_kernel<<<NRM_GRID, 256>>>(x, XNp, 0);

    // QKV projections (single merged launch), outputs in (B,H,N,D)
    gemm_qkv<<<dim3(2, 256, 3), 256, SMEM>>>(XNp, wq, wk, wv, bq, bk, bv, Qp, Kp, Vp);

    // attention (tensor-core flash)
    attn_tc<<<dim3(NTOK / 128, BB * HH), 256, ATT_SMEM>>>(Qp, Kp, Vp, AOp);

    // O projection + residual + BN2 stats, then normalize R1 -> H2
    gemm_tc<2><<<dim3(2, 256), 256, SMEM>>>(AOp, wo, bo, x, R1p, MROWS, CCH, CCH);
    bn_finalize_kernel<<<1, 256>>>(g2, beta2, 1);
    normalize_kernel<<<NRM_GRID, 256>>>(R1p, H2p, 1);

    // MLP
    gemm_tc<3><<<dim3(8, 256), 256, SMEM>>>(H2p, w1, bf1, nullptr, MIDp, MROWS, FF, CCH);
    gemm_tc<4><<<dim3(2, 256), 256, SMEM>>>(MIDp, w2, bf2, R1p, (float*)d_out, MROWS, CCH, FF);
}

// round 17
// speedup vs baseline: 1.0508x; 1.0219x over previous
#include <cuda_runtime.h>
#include <math.h>
#include <stdint.h>

#define BB   32
#define NTOK 1024
#define CCH  256
#define HH   4
#define DD   64
#define FF   1024
#define MROWS (BB * NTOK)   // 32768
#define EPSV 1e-5f

// ---------------- static device scratch ----------------
__device__ float g_acc[1024];
__device__ float g_scale1[CCH], g_shift1[CCH];
__device__ float g_scale2[CCH], g_shift2[CCH];
__device__ float g_WQt[CCH * CCH], g_WKt[CCH * CCH], g_WVt[CCH * CCH];
__device__ float g_BQt[CCH], g_BKt[CCH], g_BVt[CCH];
__device__ float g_W1t[(size_t)FF * CCH];
__device__ float g_B1t[FF];
__device__ float g_Q  [(size_t)MROWS * CCH];  // (B,H,N,D)
__device__ float g_K  [(size_t)MROWS * CCH];
__device__ float g_V  [(size_t)MROWS * CCH];
__device__ float g_AO [(size_t)MROWS * CCH];
__device__ float g_R1 [(size_t)MROWS * CCH];
__device__ float g_MID[(size_t)MROWS * FF];

// ---------------- small kernels ----------------
__global__ void zero_acc_kernel() {
    g_acc[threadIdx.x] = 0.f;
}

__global__ void bn_stats_kernel(const float* __restrict__ x) {
    int c  = threadIdx.x;
    int r0 = blockIdx.x * 128;
    const float* p = x + (size_t)r0 * CCH + c;
    float s = 0.f, q = 0.f;
#pragma unroll 4
    for (int i = 0; i < 128; i++) {
        float v = p[(size_t)i * CCH];
        s += v;
        q += v * v;
    }
    atomicAdd(&g_acc[c],        s);
    atomicAdd(&g_acc[CCH + c],  q);
}

__global__ void bn_finalize_kernel(const float* __restrict__ g,
                                   const float* __restrict__ beta, int which) {
    int c = threadIdx.x;
    float invn = 1.f / (float)MROWS;
    float mean = g_acc[which * 512 + c] * invn;
    float var  = g_acc[which * 512 + 256 + c] * invn - mean * mean;
    float sc   = g[c] * rsqrtf(var + EPSV);
    float sh   = beta[c] - mean * sc;
    if (which == 0) { g_scale1[c] = sc; g_shift1[c] = sh; }
    else            { g_scale2[c] = sc; g_shift2[c] = sh; }
}

// fold BN into weights: wout[n,k] = win[n,k]*sc[k]; bout[n] = bin[n] + sum_k win[n,k]*sh[k]
// QKV: grid (256, 3), blockIdx.y selects {q,k,v}. MLP1: grid (1024, 1) with which=1.
__global__ void wprep_kernel(const float* __restrict__ wq, const float* __restrict__ bq,
                             const float* __restrict__ wk, const float* __restrict__ bk,
                             const float* __restrict__ wv, const float* __restrict__ bv,
                             int which) {
    __shared__ float red[CCH];
    const int n = blockIdx.x;
    const int k = threadIdx.x;
    const float* sc = which ? g_scale2 : g_scale1;
    const float* sh = which ? g_shift2 : g_shift1;
    const float* win;
    const float* bin;
    float* wout;
    float* bout;
    if (which) {
        win = wq; bin = bq; wout = g_W1t; bout = g_B1t;   // wq carries w1, bq carries bf1
    } else if (blockIdx.y == 0) {
        win = wq; bin = bq; wout = g_WQt; bout = g_BQt;
    } else if (blockIdx.y == 1) {
        win = wk; bin = bk; wout = g_WKt; bout = g_BKt;
    } else {
        win = wv; bin = bv; wout = g_WVt; bout = g_BVt;
    }
    const float wv_ = win[(size_t)n * CCH + k];
    wout[(size_t)n * CCH + k] = wv_ * sc[k];
    red[k] = wv_ * sh[k];
    __syncthreads();
#pragma unroll
    for (int s = 128; s > 0; s >>= 1) {
        if (k < s) red[k] += red[k + s];
        __syncthreads();
    }
    if (k == 0) bout[n] = bin[n] + red[0];
}

// ---------------- tf32 helpers ----------------
__device__ __forceinline__ uint32_t f2tf(float x) {
    uint32_t r;
    asm("cvt.rna.tf32.f32 %0, %1;" : "=r"(r) : "f"(x));
    return r;
}

__device__ __forceinline__ void mma8(float* c, const uint32_t* a, const uint32_t* b) {
    asm volatile(
        "mma.sync.aligned.m16n8k8.row.col.f32.tf32.tf32.f32 "
        "{%0,%1,%2,%3}, {%4,%5,%6,%7}, {%8,%9}, {%0,%1,%2,%3};"
        : "+f"(c[0]), "+f"(c[1]), "+f"(c[2]), "+f"(c[3])
        : "r"(a[0]), "r"(a[1]), "r"(a[2]), "r"(a[3]), "r"(b[0]), "r"(b[1]));
}

__device__ __forceinline__ void ldsm_x4(uint32_t* r, uint32_t addr) {
    asm volatile("ldmatrix.sync.aligned.m8n8.x4.shared.b16 {%0,%1,%2,%3}, [%4];"
                 : "=r"(r[0]), "=r"(r[1]), "=r"(r[2]), "=r"(r[3]) : "r"(addr));
}

#define CP16(dst, src) \
    asm volatile("cp.async.cg.shared.global [%0], [%1], 16;" :: "r"(dst), "l"(src))
#define CPCOMMIT() asm volatile("cp.async.commit_group;")
#define CPWAIT1()  asm volatile("cp.async.wait_group 1;")

// ---------------- tf32 tensor-core NT GEMM (EXACT R8 structure) ----------------
// EPI: 2 = +bias+res, store, BN2 stats   3 = +bias, ReLU   4 = +bias+res (final out)
template<int EPI>
__global__ __launch_bounds__(256, 2)
void gemm_tc(const float* __restrict__ A, const float* __restrict__ Bw,
             const float* __restrict__ bias, const float* __restrict__ res,
             float* __restrict__ out, int M, int N, int K) {
    extern __shared__ float smem[];            // 3 stages x (A 16KB | B 16KB) = 96 KB
    __shared__ float ssum[128];
    __shared__ float ssq[128];

    const int tid  = threadIdx.x;
    const int lane = tid & 31;
    const int w    = tid >> 5;
    const int g    = lane >> 2;
    const int tk   = lane & 3;
    const int wm   = w & 1, wn = w >> 1;
    const int mw0  = wm * 64, nw0 = wn * 32;
    const int bx   = blockIdx.x, by = blockIdx.y;

    if (EPI == 2 && tid < 128) { ssum[tid] = 0.f; ssq[tid] = 0.f; }

    const int rowL = tid >> 1;
    const int colL = (tid & 1) * 16;
    const float* AptG = A  + (size_t)(by * 128 + rowL) * K + colL;
    const float* BptG = Bw + (size_t)(bx * 128 + rowL) * K + colL;
    const uint32_t sbase = (uint32_t)__cvta_generic_to_shared(smem);
    const int sw = rowL & 7;
    const uint32_t dstA0 = sbase + (uint32_t)(rowL * 32) * 4u;

    const int rsel = lane & 7;
    const int tsel = lane >> 3;
    const int rA   = mw0 + ((tsel & 1) << 3) + rsel;
    const int kA   = tsel >> 1;
    const int rB   = nw0 + ((tsel >> 1) << 3) + rsel;
    const int kB   = tsel & 1;

#define CPA(S, KT)                                                            \
    do {                                                                      \
        const uint32_t da = dstA0 + (uint32_t)(S) * 32768u;                   \
        _Pragma("unroll")                                                     \
        for (int f = 0; f < 4; f++) {                                         \
            const int k4 = (colL >> 2) + f;                                   \
            const uint32_t off = (uint32_t)((k4 ^ sw) << 2) * 4u;             \
            CP16(da + off,          AptG + (KT) + f * 4);                     \
            CP16(da + off + 16384u, BptG + (KT) + f * 4);                     \
        }                                                                     \
        CPCOMMIT();                                                           \
    } while (0)

#define COMPUTE_KS(KS)                                                        \
    do {                                                                      \
        const uint32_t axor = (uint32_t)(((((KS) << 1) | kA) ^ rsel) << 4);   \
        const uint32_t bxor = (uint32_t)(((((KS) << 1) | kB) ^ rsel) << 4);   \
        uint32_t bq[8];                                                       \
        ldsm_x4(bq,     sBst + (uint32_t)(rB * 128) + bxor);                  \
        ldsm_x4(bq + 4, sBst + (uint32_t)((rB + 16) * 128) + bxor);           \
        _Pragma("unroll")                                                     \
        for (int i = 0; i < 4; i++) {                                         \
            uint32_t af[4];                                                   \
            ldsm_x4(af, sAst + (uint32_t)((rA + 16 * i) * 128) + axor);       \
            mma8(acc[i][0], af, bq);                                          \
            mma8(acc[i][1], af, bq + 2);                                      \
            mma8(acc[i][2], af, bq + 4);                                      \
            mma8(acc[i][3], af, bq + 6);                                      \
        }                                                                     \
    } while (0)

    float acc[4][4][4];
#pragma unroll
    for (int i = 0; i < 4; i++)
#pragma unroll
        for (int j = 0; j < 4; j++)
#pragma unroll
            for (int q = 0; q < 4; q++) acc[i][j][q] = 0.f;

    CPA(0, 0);
    CPA(1, 32);

    const int T = K >> 5;
    int st = 0;
    for (int t = 0; t < T; t++) {
        CPWAIT1();
        __syncthreads();
        if (t + 2 < T) {
            const int s2 = (st == 0) ? 2 : st - 1;
            CPA(s2, (t + 2) * 32);
        } else {
            CPCOMMIT();
        }
        const uint32_t sAst = sbase + (uint32_t)st * 32768u;
        const uint32_t sBst = sAst + 16384u;
        COMPUTE_KS(0);
        COMPUTE_KS(1);
        COMPUTE_KS(2);
        COMPUTE_KS(3);
        st = (st == 2) ? 0 : st + 1;
    }
#undef CPA
#undef COMPUTE_KS

    const int r_base = by * 128 + mw0 + g;
    const int c_glob = bx * 128 + nw0 + 2 * tk;
#pragma unroll
    for (int j = 0; j < 4; j++) {
        const int c0 = c_glob + j * 8;
        const float bv0 = bias[c0], bv1 = bias[c0 + 1];
        float cs0 = 0.f, cq0 = 0.f, cs1 = 0.f, cq1 = 0.f;
#pragma unroll
        for (int i = 0; i < 4; i++) {
#pragma unroll
            for (int rr = 0; rr < 2; rr++) {
                const int m = r_base + i * 16 + rr * 8;
                float v0 = acc[i][j][rr * 2 + 0] + bv0;
                float v1 = acc[i][j][rr * 2 + 1] + bv1;
                if (EPI == 2 || EPI == 4) {
                    const float2 rv = *(const float2*)(res + (size_t)m * N + c0);
                    v0 += rv.x; v1 += rv.y;
                }
                if (EPI == 3) { v0 = fmaxf(v0, 0.f); v1 = fmaxf(v1, 0.f); }
                float2 t2; t2.x = v0; t2.y = v1;
                *(float2*)(out + (size_t)m * N + c0) = t2;
                if (EPI == 2) { cs0 += v0; cq0 += v0 * v0; cs1 += v1; cq1 += v1 * v1; }
            }
        }
        if (EPI == 2) {
            const int lc = nw0 + j * 8 + 2 * tk;
            atomicAdd(&ssum[lc],     cs0); atomicAdd(&ssq[lc],     cq0);
            atomicAdd(&ssum[lc + 1], cs1); atomicAdd(&ssq[lc + 1], cq1);
        }
    }
    if (EPI == 2) {
        __syncthreads();
        if (tid < 128) {
            atomicAdd(&g_acc[512 + bx * 128 + tid], ssum[tid]);
            atomicAdd(&g_acc[768 + bx * 128 + tid], ssq[tid]);
        }
    }
}

// ---------------- merged QKV GEMM: blockIdx.z selects {w,b,out}; (B,H,N,D) scatter ----------------
__global__ __launch_bounds__(256, 2)
void gemm_qkv(const float* __restrict__ A,
              const float* __restrict__ w0, const float* __restrict__ w1, const float* __restrict__ w2,
              const float* __restrict__ b0, const float* __restrict__ b1, const float* __restrict__ b2,
              float* __restrict__ o0, float* __restrict__ o1, float* __restrict__ o2) {
    extern __shared__ float smem[];
    const int K = CCH;
    const float* Bw   = (blockIdx.z == 0) ? w0 : (blockIdx.z == 1) ? w1 : w2;
    const float* bias = (blockIdx.z == 0) ? b0 : (blockIdx.z == 1) ? b1 : b2;
    float* out        = (blockIdx.z == 0) ? o0 : (blockIdx.z == 1) ? o1 : o2;

    const int tid  = threadIdx.x;
    const int lane = tid & 31;
    const int w    = tid >> 5;
    const int g    = lane >> 2;
    const int tk   = lane & 3;
    const int wm   = w & 1, wn = w >> 1;
    const int mw0  = wm * 64, nw0 = wn * 32;
    const int bx   = blockIdx.x, by = blockIdx.y;

    const int rowL = tid >> 1;
    const int colL = (tid & 1) * 16;
    const float* AptG = A  + (size_t)(by * 128 + rowL) * K + colL;
    const float* BptG = Bw + (size_t)(bx * 128 + rowL) * K + colL;
    const uint32_t sbase = (uint32_t)__cvta_generic_to_shared(smem);
    const int sw = rowL & 7;
    const uint32_t dstA0 = sbase + (uint32_t)(rowL * 32) * 4u;

    const int rsel = lane & 7;
    const int tsel = lane >> 3;
    const int rA   = mw0 + ((tsel & 1) << 3) + rsel;
    const int kA   = tsel >> 1;
    const int rB   = nw0 + ((tsel >> 1) << 3) + rsel;
    const int kB   = tsel & 1;

#define CPA(S, KT)                                                            \
    do {                                                                      \
        const uint32_t da = dstA0 + (uint32_t)(S) * 32768u;                   \
        _Pragma("unroll")                                                     \
        for (int f = 0; f < 4; f++) {                                         \
            const int k4 = (colL >> 2) + f;                                   \
            const uint32_t off = (uint32_t)((k4 ^ sw) << 2) * 4u;             \
            CP16(da + off,          AptG + (KT) + f * 4);                     \
            CP16(da + off + 16384u, BptG + (KT) + f * 4);                     \
        }                                                                     \
        CPCOMMIT();                                                           \
    } while (0)

#define COMPUTE_KS(KS)                                                        \
    do {                                                                      \
        const uint32_t axor = (uint32_t)(((((KS) << 1) | kA) ^ rsel) << 4);   \
        const uint32_t bxor = (uint32_t)(((((KS) << 1) | kB) ^ rsel) << 4);   \
        uint32_t bq[8];                                                       \
        ldsm_x4(bq,     sBst + (uint32_t)(rB * 128) + bxor);                  \
        ldsm_x4(bq + 4, sBst + (uint32_t)((rB + 16) * 128) + bxor);           \
        _Pragma("unroll")                                                     \
        for (int i = 0; i < 4; i++) {                                         \
            uint32_t af[4];                                                   \
            ldsm_x4(af, sAst + (uint32_t)((rA + 16 * i) * 128) + axor);       \
            mma8(acc[i][0], af, bq);                                          \
            mma8(acc[i][1], af, bq + 2);                                      \
            mma8(acc[i][2], af, bq + 4);                                      \
            mma8(acc[i][3], af, bq + 6);                                      \
        }                                                                     \
    } while (0)

    float acc[4][4][4];
#pragma unroll
    for (int i = 0; i < 4; i++)
#pragma unroll
        for (int j = 0; j < 4; j++)
#pragma unroll
            for (int q = 0; q < 4; q++) acc[i][j][q] = 0.f;

    CPA(0, 0);
    CPA(1, 32);

    const int T = K >> 5;   // 8
    int st = 0;
    for (int t = 0; t < T; t++) {
        CPWAIT1();
        __syncthreads();
        if (t + 2 < T) {
            const int s2 = (st == 0) ? 2 : st - 1;
            CPA(s2, (t + 2) * 32);
        } else {
            CPCOMMIT();
        }
        const uint32_t sAst = sbase + (uint32_t)st * 32768u;
        const uint32_t sBst = sAst + 16384u;
        COMPUTE_KS(0);
        COMPUTE_KS(1);
        COMPUTE_KS(2);
        COMPUTE_KS(3);
        st = (st == 2) ? 0 : st + 1;
    }
#undef CPA
#undef COMPUTE_KS

    const int r_base = by * 128 + mw0 + g;
    const int c_glob = bx * 128 + nw0 + 2 * tk;
#pragma unroll
    for (int j = 0; j < 4; j++) {
        const int c0 = c_glob + j * 8;
        const float bv0 = bias[c0], bv1 = bias[c0 + 1];
#pragma unroll
        for (int i = 0; i < 4; i++) {
#pragma unroll
            for (int rr = 0; rr < 2; rr++) {
                const int m = r_base + i * 16 + rr * 8;
                float2 t2;
                t2.x = acc[i][j][rr * 2 + 0] + bv0;
                t2.y = acc[i][j][rr * 2 + 1] + bv1;
                const int h = c0 >> 6, d = c0 & 63;
                const int b = m >> 10, n = m & 1023;
                *(float2*)(out + (((size_t)(b * HH + h) * NTOK + n) * DD + d)) = t2;
            }
        }
    }
}

// ---------------- tensor-core flash attention (EXACT R15-passing version) ----------------
#define KS_STRIDE 68
#define VS_STRIDE 132
#define ATT_SMEM ((128 * KS_STRIDE + 64 * VS_STRIDE) * 4)

__global__ __launch_bounds__(256, 1)
void attn_tc(const float* __restrict__ Q, const float* __restrict__ Kg,
             const float* __restrict__ Vg, float* __restrict__ O) {
    extern __shared__ float smem[];
    float* Ks = smem;
    float* Vs = smem + 128 * KS_STRIDE;

    const int tid  = threadIdx.x;
    const int lane = tid & 31;
    const int w    = tid >> 5;
    const int g    = lane >> 2;
    const int tk   = lane & 3;
    const int bh   = blockIdx.y;
    const int qt   = blockIdx.x;
    const int b    = bh >> 2, h = bh & 3;
    const size_t hoff = (size_t)bh * NTOK * DD;
    const float* Qh = Q  + hoff;
    const float* Kh = Kg + hoff;
    const float* Vh = Vg + hoff;
    const int q0 = qt * 128;

    float4 kst[8], vst[8];

#define AFETCH(KT)                                                              \
    do {                                                                        \
        _Pragma("unroll")                                                       \
        for (int i = 0; i < 8; i++) {                                           \
            const int lin = tid + 256 * i;                                      \
            const int kr = lin >> 4, c4 = lin & 15;                             \
            kst[i] = *(const float4*)(Kh + (size_t)((KT) + kr) * DD + c4 * 4);  \
            const int vc4 = lin >> 7, vk = lin & 127;                           \
            vst[i] = *(const float4*)(Vh + (size_t)((KT) + vk) * DD + vc4 * 4); \
        }                                                                       \
    } while (0)

#define ASTORE()                                                                \
    do {                                                                        \
        _Pragma("unroll")                                                       \
        for (int i = 0; i < 8; i++) {                                           \
            const int lin = tid + 256 * i;                                      \
            const int kr = lin >> 4, c4 = lin & 15;                             \
            uint4 t4; t4.x = f2tf(kst[i].x); t4.y = f2tf(kst[i].y);             \
                      t4.z = f2tf(kst[i].z); t4.w = f2tf(kst[i].w);             \
            *(uint4*)(Ks + kr * KS_STRIDE + c4 * 4) = t4;                       \
            const int vc4 = lin >> 7, vk = lin & 127;                           \
            Vs[(vc4 * 4 + 0) * VS_STRIDE + vk] = __uint_as_float(f2tf(vst[i].x)); \
            Vs[(vc4 * 4 + 1) * VS_STRIDE + vk] = __uint_as_float(f2tf(vst[i].y)); \
            Vs[(vc4 * 4 + 2) * VS_STRIDE + vk] = __uint_as_float(f2tf(vst[i].z)); \
            Vs[(vc4 * 4 + 3) * VS_STRIDE + vk] = __uint_as_float(f2tf(vst[i].w)); \
        }                                                                       \
    } while (0)

    AFETCH(0);

#pragma unroll
    for (int i = 0; i < 8; i++) {
        const int lin = tid + 256 * i;
        const int r = lin >> 4, c4 = lin & 15;
        float4 qv = *(const float4*)(Qh + (size_t)(q0 + r) * DD + c4 * 4);
        uint4 t4;
        t4.x = f2tf(qv.x * 0.125f); t4.y = f2tf(qv.y * 0.125f);
        t4.z = f2tf(qv.z * 0.125f); t4.w = f2tf(qv.w * 0.125f);
        *(uint4*)(Ks + r * KS_STRIDE + c4 * 4) = t4;
    }
    __syncthreads();

    uint32_t qa[8][4];
    {
        const float* qr0 = Ks + (w * 16 + g) * KS_STRIDE;
        const float* qr1 = qr0 + 8 * KS_STRIDE;
#pragma unroll
        for (int ks = 0; ks < 8; ks++) {
            qa[ks][0] = __float_as_uint(qr0[ks * 8 + tk]);
            qa[ks][1] = __float_as_uint(qr1[ks * 8 + tk]);
            qa[ks][2] = __float_as_uint(qr0[ks * 8 + tk + 4]);
            qa[ks][3] = __float_as_uint(qr1[ks * 8 + tk + 4]);
        }
    }

    float oacc[8][4];
#pragma unroll
    for (int n = 0; n < 8; n++)
#pragma unroll
        for (int q = 0; q < 4; q++) oacc[n][q] = 0.f;
    float m_g = -INFINITY, m_h = -INFINITY, l_g = 0.f, l_h = 0.f;

    const int src0 = (lane & 28) | (tk >> 1);
    const int src1 = src0 + 2;
    const bool odd = (tk & 1);

#pragma unroll 1
    for (int kt8 = 0; kt8 < 8; kt8++) {
        __syncthreads();
        ASTORE();
        __syncthreads();
        if (kt8 < 7) AFETCH((kt8 + 1) * 128);

        float sacc[16][4];
#pragma unroll
        for (int j = 0; j < 16; j++)
#pragma unroll
            for (int q = 0; q < 4; q++) sacc[j][q] = 0.f;

#pragma unroll
        for (int j = 0; j < 16; j++) {
            const float* krow = Ks + (j * 8 + g) * KS_STRIDE;
#pragma unroll
            for (int ks = 0; ks < 8; ks++) {
                uint32_t kb[2];
                kb[0] = __float_as_uint(krow[ks * 8 + tk]);
                kb[1] = __float_as_uint(krow[ks * 8 + tk + 4]);
                mma8(sacc[j], qa[ks], kb);
            }
        }

        float tg = -INFINITY, th = -INFINITY;
#pragma unroll
        for (int j = 0; j < 16; j++) {
            tg = fmaxf(tg, fmaxf(sacc[j][0], sacc[j][1]));
            th = fmaxf(th, fmaxf(sacc[j][2], sacc[j][3]));
        }
        tg = fmaxf(tg, __shfl_xor_sync(0xffffffffu, tg, 1));
        tg = fmaxf(tg, __shfl_xor_sync(0xffffffffu, tg, 2));
        th = fmaxf(th, __shfl_xor_sync(0xffffffffu, th, 1));
        th = fmaxf(th, __shfl_xor_sync(0xffffffffu, th, 2));
        const float mg_new = fmaxf(m_g, tg);
        const float mh_new = fmaxf(m_h, th);
        const float cg = __expf(m_g - mg_new);
        const float ch = __expf(m_h - mh_new);
        m_g = mg_new; m_h = mh_new;
        l_g *= cg; l_h *= ch;
#pragma unroll
        for (int n = 0; n < 8; n++) {
            oacc[n][0] *= cg; oacc[n][1] *= cg;
            oacc[n][2] *= ch; oacc[n][3] *= ch;
        }
#pragma unroll
        for (int j = 0; j < 16; j++) {
            const float p0 = __expf(sacc[j][0] - m_g);
            const float p1 = __expf(sacc[j][1] - m_g);
            const float p2 = __expf(sacc[j][2] - m_h);
            const float p3 = __expf(sacc[j][3] - m_h);
            l_g += p0 + p1;  l_h += p2 + p3;
            sacc[j][0] = __uint_as_float(f2tf(p0));
            sacc[j][1] = __uint_as_float(f2tf(p1));
            sacc[j][2] = __uint_as_float(f2tf(p2));
            sacc[j][3] = __uint_as_float(f2tf(p3));
        }

#pragma unroll
        for (int ks = 0; ks < 16; ks++) {
            const float e00 = __shfl_sync(0xffffffffu, sacc[ks][0], src0);
            const float e01 = __shfl_sync(0xffffffffu, sacc[ks][1], src0);
            const float e10 = __shfl_sync(0xffffffffu, sacc[ks][2], src0);
            const float e11 = __shfl_sync(0xffffffffu, sacc[ks][3], src0);
            const float f00 = __shfl_sync(0xffffffffu, sacc[ks][0], src1);
            const float f01 = __shfl_sync(0xffffffffu, sacc[ks][1], src1);
            const float f10 = __shfl_sync(0xffffffffu, sacc[ks][2], src1);
            const float f11 = __shfl_sync(0xffffffffu, sacc[ks][3], src1);
            uint32_t pa[4];
            pa[0] = __float_as_uint(odd ? e01 : e00);
            pa[1] = __float_as_uint(odd ? e11 : e10);
            pa[2] = __float_as_uint(odd ? f01 : f00);
            pa[3] = __float_as_uint(odd ? f11 : f10);
#pragma unroll
            for (int n = 0; n < 8; n++) {
                const float* vr = Vs + (n * 8 + g) * VS_STRIDE + ks * 8;
                uint32_t vb[2];
                vb[0] = __float_as_uint(vr[tk]);
                vb[1] = __float_as_uint(vr[tk + 4]);
                mma8(oacc[n], pa, vb);
            }
        }
    }
#undef AFETCH
#undef ASTORE

    l_g += __shfl_xor_sync(0xffffffffu, l_g, 1);
    l_g += __shfl_xor_sync(0xffffffffu, l_g, 2);
    l_h += __shfl_xor_sync(0xffffffffu, l_h, 1);
    l_h += __shfl_xor_sync(0xffffffffu, l_h, 2);
    const float ig = 1.f / l_g;
    const float ih = 1.f / l_h;

    const int rg = b * NTOK + q0 + w * 16 + g;
    const int cbase = h * DD + 2 * tk;
#pragma unroll
    for (int n = 0; n < 8; n++) {
        float2 t0; t0.x = oacc[n][0] * ig; t0.y = oacc[n][1] * ig;
        *(float2*)(O + (size_t)rg * CCH + cbase + n * 8) = t0;
        float2 t1; t1.x = oacc[n][2] * ih; t1.y = oacc[n][3] * ih;
        *(float2*)(O + (size_t)(rg + 8) * CCH + cbase + n * 8) = t1;
    }
}

// ---------------- host launcher ----------------
extern "C" void kernel_launch(void* const* d_in, const int* in_sizes, int n_in,
                              void* d_out, int out_size) {
    const float* x     = (const float*)d_in[0];
    const float* wq    = (const float*)d_in[1];
    const float* bq    = (const float*)d_in[2];
    const float* wk    = (const float*)d_in[3];
    const float* bk    = (const float*)d_in[4];
    const float* wv    = (const float*)d_in[5];
    const float* bv    = (const float*)d_in[6];
    const float* wo    = (const float*)d_in[7];
    const float* bo    = (const float*)d_in[8];
    const float* g1    = (const float*)d_in[9];
    const float* beta1 = (const float*)d_in[10];
    const float* g2    = (const float*)d_in[11];
    const float* beta2 = (const float*)d_in[12];
    const float* w1    = (const float*)d_in[13];
    const float* bf1   = (const float*)d_in[14];
    const float* w2    = (const float*)d_in[15];
    const float* bf2   = (const float*)d_in[16];

    float *Qp, *Kp, *Vp, *AOp, *R1p, *MIDp;
    float *WQt, *WKt, *WVt, *BQt, *BKt, *BVt, *W1t, *B1t;
    cudaGetSymbolAddress((void**)&Qp,   g_Q);
    cudaGetSymbolAddress((void**)&Kp,   g_K);
    cudaGetSymbolAddress((void**)&Vp,   g_V);
    cudaGetSymbolAddress((void**)&AOp,  g_AO);
    cudaGetSymbolAddress((void**)&R1p,  g_R1);
    cudaGetSymbolAddress((void**)&MIDp, g_MID);
    cudaGetSymbolAddress((void**)&WQt,  g_WQt);
    cudaGetSymbolAddress((void**)&WKt,  g_WKt);
    cudaGetSymbolAddress((void**)&WVt,  g_WVt);
    cudaGetSymbolAddress((void**)&BQt,  g_BQt);
    cudaGetSymbolAddress((void**)&BKt,  g_BKt);
    cudaGetSymbolAddress((void**)&BVt,  g_BVt);
    cudaGetSymbolAddress((void**)&W1t,  g_W1t);
    cudaGetSymbolAddress((void**)&B1t,  g_B1t);

    const int SMEM = 98304;   // 3 stages x 32 KB
    cudaFuncSetAttribute(gemm_qkv,   cudaFuncAttributeMaxDynamicSharedMemorySize, SMEM);
    cudaFuncSetAttribute(gemm_tc<2>, cudaFuncAttributeMaxDynamicSharedMemorySize, SMEM);
    cudaFuncSetAttribute(gemm_tc<3>, cudaFuncAttributeMaxDynamicSharedMemorySize, SMEM);
    cudaFuncSetAttribute(gemm_tc<4>, cudaFuncAttributeMaxDynamicSharedMemorySize, SMEM);
    cudaFuncSetAttribute(attn_tc,    cudaFuncAttributeMaxDynamicSharedMemorySize, ATT_SMEM);

    // BN1: stats -> finalize -> fold into QKV weights
    zero_acc_kernel<<<1, 1024>>>();
    bn_stats_kernel<<<256, 256>>>(x);
    bn_finalize_kernel<<<1, 256>>>(g1, beta1, 0);
    wprep_kernel<<<dim3(CCH, 3), CCH>>>(wq, bq, wk, bk, wv, bv, 0);

    // QKV projections on raw x (BN folded into weights), outputs in (B,H,N,D)
    gemm_qkv<<<dim3(2, 256, 3), 256, SMEM>>>(x, WQt, WKt, WVt, BQt, BKt, BVt, Qp, Kp, Vp);

    // attention (tensor-core flash)
    attn_tc<<<dim3(NTOK / 128, BB * HH), 256, ATT_SMEM>>>(Qp, Kp, Vp, AOp);

    // O projection + residual + BN2 stats, then fold BN2 into w1
    gemm_tc<2><<<dim3(2, 256), 256, SMEM>>>(AOp, wo, bo, x, R1p, MROWS, CCH, CCH);
    bn_finalize_kernel<<<1, 256>>>(g2, beta2, 1);
    wprep_kernel<<<dim3(FF, 1), CCH>>>(w1, bf1, nullptr, nullptr, nullptr, nullptr, 1);

    // MLP on raw R1 (BN folded into w1)
    gemm_tc<3><<<dim3(8, 256), 256, SMEM>>>(R1p, W1t, B1t, nullptr, MIDp, MROWS, FF, CCH);
    gemm_tc<4><<<dim3(2, 256), 256, SMEM>>>(MIDp, w2, bf2, R1p, (float*)d_out, MROWS, CCH, FF);
}